// round 12
// baseline (speedup 1.0000x reference)
#include <cuda_runtime.h>
#include <stdint.h>

// Problem constants (fixed by the reference)
#define BATCH 128
#define NN    512
#define NBINS 100
#define WPR   (NN / 32)   // 16 words per bitset row
#define RSTR  20          // padded row stride in words (80B, 16B-aligned)
#define NBLK  256         // persistent blocks; 2/SM co-resident
#define NCHUNK 32         // 32 chunks x 8 row-pairs = 256 pairs = ALL rows
#define NBUF  3           // triple-buffered staging
#define SEGS  40          // 512B segments per chunk (8 pairs x 5 panels)

// Scratch (allocation-free: __device__ globals)
__device__ float    g_histf[2][BATCH][NBINS];
__device__ float    g_acc[3];
__device__ unsigned g_sync = 0;
__device__ unsigned g_done = 0;

struct MmdStage {
    float xs[16][NBINS + 1];
    float ys[16][NBINS + 1];
    float red[8];
};

struct Smem {
    uint4 rows4[NN][RSTR / 4];                              // 40960 B bitset
    union { float4 stage[NBUF][SEGS * 32]; MmdStage mm; } s2;  // 61440 B
};

// 32x32 bit-matrix transpose across a warp.
__device__ __forceinline__ uint32_t transpose32(uint32_t x, int lane) {
#pragma unroll
    for (int i = 16; i > 0; i >>= 1) {
        uint32_t m = (i == 16) ? 0xFFFF0000u : (i == 8) ? 0xFF00FF00u
                   : (i == 4)  ? 0xF0F0F0F0u : (i == 2) ? 0xCCCCCCCCu
                                             : 0xAAAAAAAAu;
        uint32_t y = __shfl_xor_sync(0xffffffffu, x, i);
        x = (lane & i) ? ((x & m) | ((y & m) >> i))
                       : ((x & ~m) | ((y & ~m) << i));
    }
    return x;
}

// segment -> (row, panel q). Chunk c covers row-pairs (c*8 .. c*8+7); pair t
// needs panels [0]=(t,0) if t<128 else (511-t,2), [1..3]=(t,1..3), [4]=(511-t,3).
__device__ __forceinline__ void seg_to_rowq(int s, int c, int& row, int& q) {
    int pl    = s / 5;
    int panel = s - 5 * pl;
    int t = c * 8 + pl;                 // t in 0..255 over all 32 chunks
    if (panel == 0)      { if (t < 128) { row = t; q = 0; } else { row = 511 - t; q = 2; } }
    else if (panel <= 3) { row = t;       q = panel; }
    else                 { row = 511 - t; q = 3; }
}

// ---------------------------------------------------------------------------
// ONE persistent kernel, 256 blocks (2/SM). Phase A: triple-buffered cp.async
// chunk pipeline (20KB chunks, 2 in flight while packing) feeding ballot-pack
// from warm smem. Then mirror transposes, triangles, histograms, device
// barrier, RBF-MMD tiles, last-block finalize.
// ---------------------------------------------------------------------------
__global__ void __launch_bounds__(512, 2) fused_kernel(
        const float* __restrict__ a1, const float* __restrict__ a2,
        float* __restrict__ out) {
    extern __shared__ __align__(16) char smem_raw[];
    Smem& U = *reinterpret_cast<Smem*>(smem_raw);
    __shared__ int shist[NBINS];

    int wid  = threadIdx.x >> 5;
    int lane = threadIdx.x & 31;

    if (blockIdx.x == 0 && threadIdx.x < 3) g_acc[threadIdx.x] = 0.0f;
    if (threadIdx.x < NBINS) shist[threadIdx.x] = 0;

    // ================= graph phase: ONE graph per block =================
    {
        int sb = blockIdx.x;
        int s  = sb >> 7;
        int b  = sb & (BATCH - 1);
        const char* __restrict__ base =
            reinterpret_cast<const char*>((s ? a2 : a1) + (size_t)b * NN * NN);

#define ISSUE_CHUNK(cc, buf) {                                             \
    for (int e = threadIdx.x; e < SEGS * 32; e += 512) {                   \
        int sg = e >> 5, x = e & 31;                                       \
        int row, q; seg_to_rowq(sg, (cc), row, q);                         \
        const char* g = base + row * 2048 + q * 512 + x * 16;              \
        uint32_t d = (uint32_t)__cvta_generic_to_shared(                   \
            &U.s2.stage[buf][e]);                                          \
        asm volatile("cp.async.cg.shared.global [%0], [%1], 16;"           \
                     :: "r"(d), "l"(g));                                   \
    }                                                                      \
    asm volatile("cp.async.commit_group;" ::: "memory"); }

#define PACK_CHUNK(cc, buf) {                                              \
    for (int sg = wid; sg < SEGS; sg += 16) {                              \
        int row, q; seg_to_rowq(sg, (cc), row, q);                         \
        float4 v = U.s2.stage[buf][sg * 32 + lane];                        \
        uint32_t bx = __ballot_sync(0xffffffffu, v.x != 0.0f);             \
        uint32_t by = __ballot_sync(0xffffffffu, v.y != 0.0f);             \
        uint32_t bz = __ballot_sync(0xffffffffu, v.z != 0.0f);             \
        uint32_t bw = __ballot_sync(0xffffffffu, v.w != 0.0f);             \
        if (lane == 0) U.rows4[row][q] = make_uint4(bx, by, bz, bw);       \
    } }

        // ---- Phase A: triple-buffered cp.async pipeline ----
        ISSUE_CHUNK(0, 0);
        ISSUE_CHUNK(1, 1);
        ISSUE_CHUNK(2, 2);
        int buf = 0;
#pragma unroll 1
        for (int c = 0; c < NCHUNK; ++c) {
            // chunk c complete when pending groups <= (#issued-after) - c - 1
            if (c < NCHUNK - 2)
                asm volatile("cp.async.wait_group 2;" ::: "memory");
            else if (c == NCHUNK - 2)
                asm volatile("cp.async.wait_group 1;" ::: "memory");
            else
                asm volatile("cp.async.wait_group 0;" ::: "memory");
            __syncthreads();                 // chunk c visible to all
            PACK_CHUNK(c, buf);
            __syncthreads();                 // buffer free before reuse
            if (c + NBUF < NCHUNK) ISSUE_CHUNK(c + NBUF, buf);
            buf = (buf == NBUF - 1) ? 0 : buf + 1;
        }

        // ---- Phase M: mirror lower panels (R,Q), Q<R, from upper (Q,R) ----
        if (wid < 6) {
            const int RT[6] = {1, 2, 2, 3, 3, 3};
            const int QT[6] = {0, 0, 1, 0, 1, 2};
            int R = RT[wid], Q = QT[wid];
            uint4 u0 = U.rows4[128 * Q + 4 * lane + 0][R];
            uint4 u1 = U.rows4[128 * Q + 4 * lane + 1][R];
            uint4 u2 = U.rows4[128 * Q + 4 * lane + 2][R];
            uint4 u3 = U.rows4[128 * Q + 4 * lane + 3][R];
            u0.x = transpose32(u0.x, lane); u0.y = transpose32(u0.y, lane);
            u0.z = transpose32(u0.z, lane); u0.w = transpose32(u0.w, lane);
            u1.x = transpose32(u1.x, lane); u1.y = transpose32(u1.y, lane);
            u1.z = transpose32(u1.z, lane); u1.w = transpose32(u1.w, lane);
            u2.x = transpose32(u2.x, lane); u2.y = transpose32(u2.y, lane);
            u2.z = transpose32(u2.z, lane); u2.w = transpose32(u2.w, lane);
            u3.x = transpose32(u3.x, lane); u3.y = transpose32(u3.y, lane);
            u3.z = transpose32(u3.z, lane); u3.w = transpose32(u3.w, lane);
            U.rows4[128 * R + 4 * lane + 0][Q] = make_uint4(u0.x, u1.x, u2.x, u3.x);
            U.rows4[128 * R + 4 * lane + 1][Q] = make_uint4(u0.y, u1.y, u2.y, u3.y);
            U.rows4[128 * R + 4 * lane + 2][Q] = make_uint4(u0.z, u1.z, u2.z, u3.z);
            U.rows4[128 * R + 4 * lane + 3][Q] = make_uint4(u0.w, u1.w, u2.w, u3.w);
        }
        __syncthreads();

        // ---- Phase B: triangles. One thread per node, uniform trips. ----
        int i = threadIdx.x;
        uint32_t my[WPR];
        int deg = 0;
        {
            const uint4* r4 = U.rows4[i];
#pragma unroll
            for (int k = 0; k < 4; ++k) {
                uint4 v = r4[k];
                my[4*k]   = v.x; my[4*k+1] = v.y; my[4*k+2] = v.z; my[4*k+3] = v.w;
                deg += __popc(v.x) + __popc(v.y) + __popc(v.z) + __popc(v.w);
            }
        }

        int tri = 0;
        {
            int w = 0;
            uint32_t m = my[0];
            for (int n = 0; n < deg; ++n) {
                while (m == 0) m = my[++w];
                int l = __ffs(m) - 1;
                m &= m - 1;
                int j = (w >> 2) * 128 + 4 * l + (w & 3);   // perm inverse
                const uint4* rj = U.rows4[j];
                int c = 0;
#pragma unroll
                for (int k = 0; k < 4; ++k) {
                    uint4 v = rj[k];                        // LDS.128
                    c += __popc(my[4*k]   & v.x) + __popc(my[4*k+1] & v.y)
                       + __popc(my[4*k+2] & v.z) + __popc(my[4*k+3] & v.w);
                }
                tri += c;
            }
        }

        // ---- Phase C: bin (IEEE-exact vs JAX fp32) + histogram ----
        int bin = 0;
        if (deg >= 2) {
            float denom = (float)deg * (float)(deg - 1);
            float c  = __fdiv_rn((float)tri, denom);
            float cb = __fmul_rn(c, (float)NBINS);
            bin = (int)cb;
            bin = bin < 0 ? 0 : (bin > NBINS - 1 ? NBINS - 1 : bin);
        }
        atomicAdd(&shist[bin], 1);
        __syncthreads();

        if (threadIdx.x < NBINS)
            g_histf[s][b][threadIdx.x] = (float)shist[threadIdx.x];
        __syncthreads();
    }

    // ============ device-wide barrier (all 256 blocks co-resident) ============
    if (threadIdx.x == 0) {
        __threadfence();
        atomicAdd(&g_sync, 1u);
        while (*(volatile unsigned*)&g_sync < (unsigned)NBLK) { }
    }
    __syncthreads();
    __threadfence();

    // ================= mmd phase: blocks 0..191 do one tile each ============
    int t = threadIdx.x;
    if (blockIdx.x < 192) {
        int tile = blockIdx.x;
        int m  = tile >> 6;
        int r  = tile & 63;
        int i0 = (r >> 3) << 4;
        int j0 = (r & 7) << 4;

        const float* __restrict__ hx0 = &g_histf[(m == 1) ? 1 : 0][0][0];
        const float* __restrict__ hy0 = &g_histf[(m == 0) ? 0 : 1][0][0];

        for (int e = t; e < 16 * NBINS; e += 512) {
            int rr = e / NBINS, k = e % NBINS;
            U.s2.mm.xs[rr][k] = hx0[(i0 + rr) * NBINS + k];
            U.s2.mm.ys[rr][k] = hy0[(j0 + rr) * NBINS + k];
        }
        __syncthreads();

        float kv = 0.0f;
        if (t < 256) {
            int ti = t >> 4, tj = t & 15;
            float d2 = 0.0f;
#pragma unroll 4
            for (int k = 0; k < NBINS; ++k) {
                float d = U.s2.mm.xs[ti][k] - U.s2.mm.ys[tj][k];
                d2 = fmaf(d, d, d2);
            }
            kv = expf(-0.5f * d2);
        }
#pragma unroll
        for (int o = 16; o; o >>= 1)
            kv += __shfl_down_sync(0xffffffffu, kv, o);
        if ((t & 31) == 0) U.s2.mm.red[t >> 5] = (t < 256) ? kv : 0.0f;
        __syncthreads();
        if (t < 32) {
            float v = (t < 8) ? U.s2.mm.red[t] : 0.0f;
#pragma unroll
            for (int o = 4; o; o >>= 1)
                v += __shfl_down_sync(0xffffffffu, v, o);
            if (t == 0) atomicAdd(&g_acc[m], v);
        }
        __syncthreads();
    }

    // last-block-out finalize + counter reset (replay-deterministic)
    if (t == 0) {
        __threadfence();
        unsigned tk = atomicAdd(&g_done, 1u);
        if (tk == (unsigned)(NBLK - 1)) {
            __threadfence();
            const float inv = 1.0f / (128.0f * 128.0f);
            out[0] = (g_acc[0] + g_acc[1] - 2.0f * g_acc[2]) * inv;
            g_done = 0;
            g_sync = 0;
        }
    }
}

// ---------------------------------------------------------------------------
extern "C" void kernel_launch(void* const* d_in, const int* in_sizes, int n_in,
                              void* d_out, int out_size) {
    const float* a1 = (const float*)d_in[0];
    const float* a2 = (const float*)d_in[1];

    cudaFuncSetAttribute(fused_kernel,
                         cudaFuncAttributeMaxDynamicSharedMemorySize,
                         (int)sizeof(Smem));
    fused_kernel<<<NBLK, 512, sizeof(Smem)>>>(a1, a2, (float*)d_out);
}

// round 13
// speedup vs baseline: 1.0426x; 1.0426x over previous
#include <cuda_runtime.h>
#include <stdint.h>

// Problem constants (fixed by the reference)
#define BATCH 128
#define NN    512
#define NBINS 100
#define WPR   (NN / 32)   // 16 words per bitset row
#define RSTR  20          // padded row stride in words (80B, 16B-aligned)
#define NBLK  256         // persistent blocks; 2/SM co-resident
#define SEGW  80          // 512B segments per warp (16 pairs x 5 panels)
#define DEPTH 8           // per-warp cp.async pipeline depth

// Scratch (allocation-free: __device__ globals)
__device__ float    g_histf[2][BATCH][NBINS];
__device__ float    g_acc[3];
__device__ unsigned g_sync = 0;
__device__ unsigned g_done = 0;

struct MmdStage {
    float xs[16][NBINS + 1];
    float ys[16][NBINS + 1];
    float red[8];
};

struct Smem {
    uint4 rows4[NN][RSTR / 4];                               // 40960 B bitset
    union { float4 stage[16][DEPTH][32]; MmdStage mm; } s2;  // 65536 B
};

// 32x32 bit-matrix transpose across a warp.
__device__ __forceinline__ uint32_t transpose32(uint32_t x, int lane) {
#pragma unroll
    for (int i = 16; i > 0; i >>= 1) {
        uint32_t m = (i == 16) ? 0xFFFF0000u : (i == 8) ? 0xFF00FF00u
                   : (i == 4)  ? 0xF0F0F0F0u : (i == 2) ? 0xCCCCCCCCu
                                             : 0xAAAAAAAAu;
        uint32_t y = __shfl_xor_sync(0xffffffffu, x, i);
        x = (lane & i) ? ((x & m) | ((y & m) >> i))
                       : ((x & ~m) | ((y & ~m) << i));
    }
    return x;
}

// Per-warp segment s (0..79) -> (row, panel q). Warp wid owns row-pairs
// t = wid*16 + s/5; pair t needs panels [0]=(t,0) if t<128 else (511-t,2),
// [1..3]=(t,1..3), [4]=(511-t,3).  (Coverage verified: rel_err 0.0 in R12.)
__device__ __forceinline__ void seg_to_rowq(int s, int wid, int& row, int& q) {
    int pl    = s / 5;                 // const-div -> mul-high, cheap
    int panel = s - 5 * pl;
    int t = wid * 16 + pl;             // 0..255
    if (panel == 0)      { if (t < 128) { row = t; q = 0; } else { row = 511 - t; q = 2; } }
    else if (panel <= 3) { row = t;       q = panel; }
    else                 { row = 511 - t; q = 3; }
}

// ---------------------------------------------------------------------------
// ONE persistent kernel, 256 blocks (2/SM). Phase A: PER-WARP depth-8
// cp.async pipelines -- each lane packs the 16B it itself copied, so the only
// sync is the thread's own wait_group; ZERO block barriers until phase end.
// Then mirror transposes, triangles, histograms, device barrier, RBF tiles.
// ---------------------------------------------------------------------------
__global__ void __launch_bounds__(512, 2) fused_kernel(
        const float* __restrict__ a1, const float* __restrict__ a2,
        float* __restrict__ out) {
    extern __shared__ __align__(16) char smem_raw[];
    Smem& U = *reinterpret_cast<Smem*>(smem_raw);
    __shared__ int shist[NBINS];

    int wid  = threadIdx.x >> 5;
    int lane = threadIdx.x & 31;

    if (blockIdx.x == 0 && threadIdx.x < 3) g_acc[threadIdx.x] = 0.0f;
    if (threadIdx.x < NBINS) shist[threadIdx.x] = 0;

    // ================= graph phase: ONE graph per block =================
    {
        int sb = blockIdx.x;
        int s_ = sb >> 7;
        int b  = sb & (BATCH - 1);
        const char* __restrict__ base =
            reinterpret_cast<const char*>((s_ ? a2 : a1) + (size_t)b * NN * NN);

#define ISSUE_SEG(ss) {                                                    \
    int row, q; seg_to_rowq((ss), wid, row, q);                            \
    const char* g = base + row * 2048 + q * 512 + lane * 16;               \
    uint32_t d = (uint32_t)__cvta_generic_to_shared(                       \
        &U.s2.stage[wid][(ss) & (DEPTH - 1)][lane]);                       \
    asm volatile("cp.async.cg.shared.global [%0], [%1], 16;\n\t"           \
                 "cp.async.commit_group;" :: "r"(d), "l"(g) : "memory"); }

        // ---- Phase A: per-warp pipeline, no block barriers ----
#pragma unroll
        for (int p = 0; p < DEPTH; ++p) ISSUE_SEG(p);
#pragma unroll 1
        for (int s = 0; s < SEGW; ++s) {
            if (s < SEGW - DEPTH)
                asm volatile("cp.async.wait_group %0;" :: "n"(DEPTH - 1) : "memory");
            else
                asm volatile("cp.async.wait_group 0;" ::: "memory");
            float4 v = U.s2.stage[wid][s & (DEPTH - 1)][lane];  // own 16B
            uint32_t bx = __ballot_sync(0xffffffffu, v.x != 0.0f);
            uint32_t by = __ballot_sync(0xffffffffu, v.y != 0.0f);
            uint32_t bz = __ballot_sync(0xffffffffu, v.z != 0.0f);
            uint32_t bw = __ballot_sync(0xffffffffu, v.w != 0.0f);
            int row, q; seg_to_rowq(s, wid, row, q);
            if (lane == 0) U.rows4[row][q] = make_uint4(bx, by, bz, bw);
            if (s + DEPTH < SEGW) ISSUE_SEG(s + DEPTH);
        }
        __syncthreads();               // the ONLY phase-A block barrier

        // ---- Phase M: mirror lower panels (R,Q), Q<R, from upper (Q,R) ----
        if (wid < 6) {
            const int RT[6] = {1, 2, 2, 3, 3, 3};
            const int QT[6] = {0, 0, 1, 0, 1, 2};
            int R = RT[wid], Q = QT[wid];
            uint4 u0 = U.rows4[128 * Q + 4 * lane + 0][R];
            uint4 u1 = U.rows4[128 * Q + 4 * lane + 1][R];
            uint4 u2 = U.rows4[128 * Q + 4 * lane + 2][R];
            uint4 u3 = U.rows4[128 * Q + 4 * lane + 3][R];
            u0.x = transpose32(u0.x, lane); u0.y = transpose32(u0.y, lane);
            u0.z = transpose32(u0.z, lane); u0.w = transpose32(u0.w, lane);
            u1.x = transpose32(u1.x, lane); u1.y = transpose32(u1.y, lane);
            u1.z = transpose32(u1.z, lane); u1.w = transpose32(u1.w, lane);
            u2.x = transpose32(u2.x, lane); u2.y = transpose32(u2.y, lane);
            u2.z = transpose32(u2.z, lane); u2.w = transpose32(u2.w, lane);
            u3.x = transpose32(u3.x, lane); u3.y = transpose32(u3.y, lane);
            u3.z = transpose32(u3.z, lane); u3.w = transpose32(u3.w, lane);
            U.rows4[128 * R + 4 * lane + 0][Q] = make_uint4(u0.x, u1.x, u2.x, u3.x);
            U.rows4[128 * R + 4 * lane + 1][Q] = make_uint4(u0.y, u1.y, u2.y, u3.y);
            U.rows4[128 * R + 4 * lane + 2][Q] = make_uint4(u0.z, u1.z, u2.z, u3.z);
            U.rows4[128 * R + 4 * lane + 3][Q] = make_uint4(u0.w, u1.w, u2.w, u3.w);
        }
        __syncthreads();

        // ---- Phase B: triangles. One thread per node, uniform trips. ----
        int i = threadIdx.x;
        uint32_t my[WPR];
        int deg = 0;
        {
            const uint4* r4 = U.rows4[i];
#pragma unroll
            for (int k = 0; k < 4; ++k) {
                uint4 v = r4[k];
                my[4*k]   = v.x; my[4*k+1] = v.y; my[4*k+2] = v.z; my[4*k+3] = v.w;
                deg += __popc(v.x) + __popc(v.y) + __popc(v.z) + __popc(v.w);
            }
        }

        int tri = 0;
        {
            int w = 0;
            uint32_t m = my[0];
            for (int n = 0; n < deg; ++n) {
                while (m == 0) m = my[++w];
                int l = __ffs(m) - 1;
                m &= m - 1;
                int j = (w >> 2) * 128 + 4 * l + (w & 3);   // perm inverse
                const uint4* rj = U.rows4[j];
                int c = 0;
#pragma unroll
                for (int k = 0; k < 4; ++k) {
                    uint4 v = rj[k];                        // LDS.128
                    c += __popc(my[4*k]   & v.x) + __popc(my[4*k+1] & v.y)
                       + __popc(my[4*k+2] & v.z) + __popc(my[4*k+3] & v.w);
                }
                tri += c;
            }
        }

        // ---- Phase C: bin (IEEE-exact vs JAX fp32) + histogram ----
        int bin = 0;
        if (deg >= 2) {
            float denom = (float)deg * (float)(deg - 1);
            float c  = __fdiv_rn((float)tri, denom);
            float cb = __fmul_rn(c, (float)NBINS);
            bin = (int)cb;
            bin = bin < 0 ? 0 : (bin > NBINS - 1 ? NBINS - 1 : bin);
        }
        atomicAdd(&shist[bin], 1);
        __syncthreads();

        if (threadIdx.x < NBINS)
            g_histf[s_][b][threadIdx.x] = (float)shist[threadIdx.x];
        __syncthreads();
    }

    // ============ device-wide barrier (all 256 blocks co-resident) ============
    if (threadIdx.x == 0) {
        __threadfence();
        atomicAdd(&g_sync, 1u);
        while (*(volatile unsigned*)&g_sync < (unsigned)NBLK) { }
    }
    __syncthreads();
    __threadfence();

    // ================= mmd phase: blocks 0..191 do one tile each ============
    int t = threadIdx.x;
    if (blockIdx.x < 192) {
        int tile = blockIdx.x;
        int m  = tile >> 6;
        int r  = tile & 63;
        int i0 = (r >> 3) << 4;
        int j0 = (r & 7) << 4;

        const float* __restrict__ hx0 = &g_histf[(m == 1) ? 1 : 0][0][0];
        const float* __restrict__ hy0 = &g_histf[(m == 0) ? 0 : 1][0][0];

        for (int e = t; e < 16 * NBINS; e += 512) {
            int rr = e / NBINS, k = e % NBINS;
            U.s2.mm.xs[rr][k] = hx0[(i0 + rr) * NBINS + k];
            U.s2.mm.ys[rr][k] = hy0[(j0 + rr) * NBINS + k];
        }
        __syncthreads();

        float kv = 0.0f;
        if (t < 256) {
            int ti = t >> 4, tj = t & 15;
            float d2 = 0.0f;
#pragma unroll 4
            for (int k = 0; k < NBINS; ++k) {
                float d = U.s2.mm.xs[ti][k] - U.s2.mm.ys[tj][k];
                d2 = fmaf(d, d, d2);
            }
            kv = expf(-0.5f * d2);
        }
#pragma unroll
        for (int o = 16; o; o >>= 1)
            kv += __shfl_down_sync(0xffffffffu, kv, o);
        if ((t & 31) == 0) U.s2.mm.red[t >> 5] = (t < 256) ? kv : 0.0f;
        __syncthreads();
        if (t < 32) {
            float v = (t < 8) ? U.s2.mm.red[t] : 0.0f;
#pragma unroll
            for (int o = 4; o; o >>= 1)
                v += __shfl_down_sync(0xffffffffu, v, o);
            if (t == 0) atomicAdd(&g_acc[m], v);
        }
        __syncthreads();
    }

    // last-block-out finalize + counter reset (replay-deterministic)
    if (t == 0) {
        __threadfence();
        unsigned tk = atomicAdd(&g_done, 1u);
        if (tk == (unsigned)(NBLK - 1)) {
            __threadfence();
            const float inv = 1.0f / (128.0f * 128.0f);
            out[0] = (g_acc[0] + g_acc[1] - 2.0f * g_acc[2]) * inv;
            g_done = 0;
            g_sync = 0;
        }
    }
}

// ---------------------------------------------------------------------------
extern "C" void kernel_launch(void* const* d_in, const int* in_sizes, int n_in,
                              void* d_out, int out_size) {
    const float* a1 = (const float*)d_in[0];
    const float* a2 = (const float*)d_in[1];

    cudaFuncSetAttribute(fused_kernel,
                         cudaFuncAttributeMaxDynamicSharedMemorySize,
                         (int)sizeof(Smem));
    fused_kernel<<<NBLK, 512, sizeof(Smem)>>>(a1, a2, (float*)d_out);
}

// round 14
// speedup vs baseline: 1.0593x; 1.0159x over previous
#include <cuda_runtime.h>
#include <stdint.h>

// Problem constants (fixed by the reference)
#define BATCH 128
#define NN    512
#define NBINS 100
#define WPR   (NN / 32)   // 16 words per bitset row
#define RSTR  20          // padded row stride in words (80B, 16B-aligned)
#define NBLK  256         // persistent blocks; 2/SM co-resident
#define SEGW  80          // 512B segments per warp (16 pairs x 5 panels)
#define DEPTH 8           // per-warp cp.async pipeline depth (segments)

// Scratch (allocation-free: __device__ globals)
__device__ float    g_histf[2][BATCH][NBINS];
__device__ float    g_acc[3];
__device__ unsigned g_sync = 0;
__device__ unsigned g_done = 0;

struct MmdStage {
    float xs[16][NBINS + 1];
    float ys[16][NBINS + 1];
    float red[8];
};

struct Smem {
    uint4 rows4[NN][RSTR / 4];                               // 40960 B bitset
    union { float4 stage[16][DEPTH][32]; MmdStage mm; } s2;  // 65536 B
};

// 32x32 bit-matrix transpose across a warp.
__device__ __forceinline__ uint32_t transpose32(uint32_t x, int lane) {
#pragma unroll
    for (int i = 16; i > 0; i >>= 1) {
        uint32_t m = (i == 16) ? 0xFFFF0000u : (i == 8) ? 0xFF00FF00u
                   : (i == 4)  ? 0xF0F0F0F0u : (i == 2) ? 0xCCCCCCCCu
                                             : 0xAAAAAAAAu;
        uint32_t y = __shfl_xor_sync(0xffffffffu, x, i);
        x = (lane & i) ? ((x & m) | ((y & m) >> i))
                       : ((x & ~m) | ((y & ~m) << i));
    }
    return x;
}

// ---------------------------------------------------------------------------
// ONE persistent kernel, 256 blocks (2/SM). Phase A: per-warp depth-8
// cp.async pipelines with INCREMENTAL segment decode (no div-by-5, no per-seg
// cvta, warp-uniform group branch). Each lane packs the 16B it copied, so the
// only sync is its own wait_group. Then mirror, triangles, histograms,
// device barrier, RBF tiles, last-block finalize.
//
// Segment map (identical coverage to verified R12/R13): warp wid owns pairs
// t = wid*16 + pl, pl=0..15; low warps (wid<8, t<128): e=0..3 -> (t, e),
// e=4 -> (511-t, 3); high warps: e=0..2 -> (t, e+1), e=3..4 -> (511-t, e-1).
// ---------------------------------------------------------------------------
__global__ void __launch_bounds__(512, 2) fused_kernel(
        const float* __restrict__ a1, const float* __restrict__ a2,
        float* __restrict__ out) {
    extern __shared__ __align__(16) char smem_raw[];
    Smem& U = *reinterpret_cast<Smem*>(smem_raw);
    __shared__ int shist[NBINS];

    int wid  = threadIdx.x >> 5;
    int lane = threadIdx.x & 31;

    if (blockIdx.x == 0 && threadIdx.x < 3) g_acc[threadIdx.x] = 0.0f;
    if (threadIdx.x < NBINS) shist[threadIdx.x] = 0;

    // ================= graph phase: ONE graph per block =================
    {
        int sb = blockIdx.x;
        int s_ = sb >> 7;
        int b  = sb & (BATCH - 1);
        const char* __restrict__ base =
            reinterpret_cast<const char*>((s_ ? a2 : a1) + (size_t)b * NN * NN);

        const bool low = (wid < 8);
        const int  a0  = wid * 16;
        const char* gbase = base + lane * 16;
        uint32_t stage_base = (uint32_t)__cvta_generic_to_shared(
            &U.s2.stage[wid][0][0]) + (uint32_t)(lane * 16);

        int ie = 0, ipl = 0, islot = 0;   // issue-side decode state
        int pe = 0, ppl = 0, pslot = 0;   // pack-side decode state

#define ISSUE_ONE() {                                                      \
        int a_ = a0 + ipl, b_ = 511 - a_;                                  \
        int row_, q_;                                                      \
        if (low) { row_ = (ie == 4) ? b_ : a_;  q_ = (ie == 4) ? 3 : ie; } \
        else     { row_ = (ie < 3) ? a_ : b_;                              \
                   q_   = (ie < 3) ? ie + 1 : ie - 1; }                    \
        const char* g = gbase + row_ * 2048 + q_ * 512;                    \
        uint32_t d = stage_base + ((uint32_t)islot << 9);                  \
        asm volatile("cp.async.cg.shared.global [%0], [%1], 16;\n\t"       \
                     "cp.async.commit_group;" :: "r"(d), "l"(g) : "memory");\
        if (++ie == 5) { ie = 0; ++ipl; }                                  \
        islot = (islot + 1) & (DEPTH - 1); }

#define PACK_ONE() {                                                       \
        float4 v = U.s2.stage[wid][pslot][lane];   /* own 16B */           \
        uint32_t bx = __ballot_sync(0xffffffffu, v.x != 0.0f);             \
        uint32_t by = __ballot_sync(0xffffffffu, v.y != 0.0f);             \
        uint32_t bz = __ballot_sync(0xffffffffu, v.z != 0.0f);             \
        uint32_t bw = __ballot_sync(0xffffffffu, v.w != 0.0f);             \
        int a_ = a0 + ppl, b_ = 511 - a_;                                  \
        int row_, q_;                                                      \
        if (low) { row_ = (pe == 4) ? b_ : a_;  q_ = (pe == 4) ? 3 : pe; } \
        else     { row_ = (pe < 3) ? a_ : b_;                              \
                   q_   = (pe < 3) ? pe + 1 : pe - 1; }                    \
        if (lane == 0) U.rows4[row_][q_] = make_uint4(bx, by, bz, bw);     \
        if (++pe == 5) { pe = 0; ++ppl; }                                  \
        pslot = (pslot + 1) & (DEPTH - 1); }

        // ---- Phase A: prime, steady-state, tail ----
#pragma unroll
        for (int p = 0; p < DEPTH; ++p) ISSUE_ONE();
#pragma unroll 1
        for (int s = 0; s < SEGW - DEPTH; ++s) {
            asm volatile("cp.async.wait_group %0;" :: "n"(DEPTH - 1) : "memory");
            PACK_ONE();
            ISSUE_ONE();
        }
#pragma unroll 1
        for (int s = SEGW - DEPTH; s < SEGW; ++s) {
            asm volatile("cp.async.wait_group 0;" ::: "memory");
            PACK_ONE();
        }
        __syncthreads();               // the ONLY phase-A block barrier

        // ---- Phase M: mirror lower panels (R,Q), Q<R, from upper (Q,R) ----
        if (wid < 6) {
            const int RT[6] = {1, 2, 2, 3, 3, 3};
            const int QT[6] = {0, 0, 1, 0, 1, 2};
            int R = RT[wid], Q = QT[wid];
            uint4 u0 = U.rows4[128 * Q + 4 * lane + 0][R];
            uint4 u1 = U.rows4[128 * Q + 4 * lane + 1][R];
            uint4 u2 = U.rows4[128 * Q + 4 * lane + 2][R];
            uint4 u3 = U.rows4[128 * Q + 4 * lane + 3][R];
            u0.x = transpose32(u0.x, lane); u0.y = transpose32(u0.y, lane);
            u0.z = transpose32(u0.z, lane); u0.w = transpose32(u0.w, lane);
            u1.x = transpose32(u1.x, lane); u1.y = transpose32(u1.y, lane);
            u1.z = transpose32(u1.z, lane); u1.w = transpose32(u1.w, lane);
            u2.x = transpose32(u2.x, lane); u2.y = transpose32(u2.y, lane);
            u2.z = transpose32(u2.z, lane); u2.w = transpose32(u2.w, lane);
            u3.x = transpose32(u3.x, lane); u3.y = transpose32(u3.y, lane);
            u3.z = transpose32(u3.z, lane); u3.w = transpose32(u3.w, lane);
            U.rows4[128 * R + 4 * lane + 0][Q] = make_uint4(u0.x, u1.x, u2.x, u3.x);
            U.rows4[128 * R + 4 * lane + 1][Q] = make_uint4(u0.y, u1.y, u2.y, u3.y);
            U.rows4[128 * R + 4 * lane + 2][Q] = make_uint4(u0.z, u1.z, u2.z, u3.z);
            U.rows4[128 * R + 4 * lane + 3][Q] = make_uint4(u0.w, u1.w, u2.w, u3.w);
        }
        __syncthreads();

        // ---- Phase B: triangles. One thread per node, uniform trips. ----
        int i = threadIdx.x;
        uint32_t my[WPR];
        int deg = 0;
        {
            const uint4* r4 = U.rows4[i];
#pragma unroll
            for (int k = 0; k < 4; ++k) {
                uint4 v = r4[k];
                my[4*k]   = v.x; my[4*k+1] = v.y; my[4*k+2] = v.z; my[4*k+3] = v.w;
                deg += __popc(v.x) + __popc(v.y) + __popc(v.z) + __popc(v.w);
            }
        }

        int tri = 0;
        {
            int w = 0;
            uint32_t m = my[0];
            for (int n = 0; n < deg; ++n) {
                while (m == 0) m = my[++w];
                int l = __ffs(m) - 1;
                m &= m - 1;
                int j = (w >> 2) * 128 + 4 * l + (w & 3);   // perm inverse
                const uint4* rj = U.rows4[j];
                int c = 0;
#pragma unroll
                for (int k = 0; k < 4; ++k) {
                    uint4 v = rj[k];                        // LDS.128
                    c += __popc(my[4*k]   & v.x) + __popc(my[4*k+1] & v.y)
                       + __popc(my[4*k+2] & v.z) + __popc(my[4*k+3] & v.w);
                }
                tri += c;
            }
        }

        // ---- Phase C: bin (IEEE-exact vs JAX fp32) + histogram ----
        int bin = 0;
        if (deg >= 2) {
            float denom = (float)deg * (float)(deg - 1);
            float c  = __fdiv_rn((float)tri, denom);
            float cb = __fmul_rn(c, (float)NBINS);
            bin = (int)cb;
            bin = bin < 0 ? 0 : (bin > NBINS - 1 ? NBINS - 1 : bin);
        }
        atomicAdd(&shist[bin], 1);
        __syncthreads();

        if (threadIdx.x < NBINS)
            g_histf[s_][b][threadIdx.x] = (float)shist[threadIdx.x];
        __syncthreads();
    }

    // ============ device-wide barrier (all 256 blocks co-resident) ============
    if (threadIdx.x == 0) {
        __threadfence();
        atomicAdd(&g_sync, 1u);
        while (*(volatile unsigned*)&g_sync < (unsigned)NBLK) { }
    }
    __syncthreads();
    __threadfence();

    // ================= mmd phase: blocks 0..191 do one tile each ============
    int t = threadIdx.x;
    if (blockIdx.x < 192) {
        int tile = blockIdx.x;
        int m  = tile >> 6;
        int r  = tile & 63;
        int i0 = (r >> 3) << 4;
        int j0 = (r & 7) << 4;

        const float* __restrict__ hx0 = &g_histf[(m == 1) ? 1 : 0][0][0];
        const float* __restrict__ hy0 = &g_histf[(m == 0) ? 0 : 1][0][0];

        for (int e = t; e < 16 * NBINS; e += 512) {
            int rr = e / NBINS, k = e % NBINS;
            U.s2.mm.xs[rr][k] = hx0[(i0 + rr) * NBINS + k];
            U.s2.mm.ys[rr][k] = hy0[(j0 + rr) * NBINS + k];
        }
        __syncthreads();

        float kv = 0.0f;
        if (t < 256) {
            int ti = t >> 4, tj = t & 15;
            float d2 = 0.0f;
#pragma unroll 4
            for (int k = 0; k < NBINS; ++k) {
                float d = U.s2.mm.xs[ti][k] - U.s2.mm.ys[tj][k];
                d2 = fmaf(d, d, d2);
            }
            kv = expf(-0.5f * d2);
        }
#pragma unroll
        for (int o = 16; o; o >>= 1)
            kv += __shfl_down_sync(0xffffffffu, kv, o);
        if ((t & 31) == 0) U.s2.mm.red[t >> 5] = (t < 256) ? kv : 0.0f;
        __syncthreads();
        if (t < 32) {
            float v = (t < 8) ? U.s2.mm.red[t] : 0.0f;
#pragma unroll
            for (int o = 4; o; o >>= 1)
                v += __shfl_down_sync(0xffffffffu, v, o);
            if (t == 0) atomicAdd(&g_acc[m], v);
        }
        __syncthreads();
    }

    // last-block-out finalize + counter reset (replay-deterministic)
    if (t == 0) {
        __threadfence();
        unsigned tk = atomicAdd(&g_done, 1u);
        if (tk == (unsigned)(NBLK - 1)) {
            __threadfence();
            const float inv = 1.0f / (128.0f * 128.0f);
            out[0] = (g_acc[0] + g_acc[1] - 2.0f * g_acc[2]) * inv;
            g_done = 0;
            g_sync = 0;
        }
    }
}

// ---------------------------------------------------------------------------
extern "C" void kernel_launch(void* const* d_in, const int* in_sizes, int n_in,
                              void* d_out, int out_size) {
    const float* a1 = (const float*)d_in[0];
    const float* a2 = (const float*)d_in[1];

    cudaFuncSetAttribute(fused_kernel,
                         cudaFuncAttributeMaxDynamicSharedMemorySize,
                         (int)sizeof(Smem));
    fused_kernel<<<NBLK, 512, sizeof(Smem)>>>(a1, a2, (float*)d_out);
}

// round 15
// speedup vs baseline: 1.1479x; 1.0836x over previous
#include <cuda_runtime.h>
#include <stdint.h>

#define BATCH 128
#define NN    512
#define NBINS 100
#define WPR   (NN / 32)
#define RSTR  20          // smem row stride in words (80B)
#define NBLK2 256         // K2 blocks (2/SM co-resident for barrier)
#define PPW   80          // panels per warp in K1
#define PDEPTH 8          // K1 register pipeline depth

// Scratch (allocation-free __device__ globals)
__device__ uint4    g_bits4[256 * 512 * 4];    // [graph][row][q] packed, 8.4MB
__device__ float    g_histf[2][BATCH][NBINS];
__device__ float    g_acc[3];
__device__ unsigned g_sync = 0;
__device__ unsigned g_done = 0;

__device__ __forceinline__ uint32_t transpose32(uint32_t x, int lane) {
#pragma unroll
    for (int i = 16; i > 0; i >>= 1) {
        uint32_t m = (i == 16) ? 0xFFFF0000u : (i == 8) ? 0xFF00FF00u
                   : (i == 4)  ? 0xF0F0F0F0u : (i == 2) ? 0xCCCCCCCCu
                                             : 0xAAAAAAAAu;
        uint32_t y = __shfl_xor_sync(0xffffffffu, x, i);
        x = (lane & i) ? ((x & m) | ((y & m) >> i))
                       : ((x & ~m) | ((y & ~m) << i));
    }
    return x;
}

// ---------------------------------------------------------------------------
// K1: pack upper panels (q >= row>>7) of all 256 graphs into g_bits4.
// 1024 blocks x 128 thr (8/SM, 1.2% ragged). Each warp: 80 panels (512B),
// depth-8 register LDG pipeline, ballot pack, lane-0 STG.128.
// Panel order per graph: [q0 rows0-127][q1 0-255][q2 0-383][q3 0-511] (1280).
// Block bid owns graph bid>>2, quarter (bid&3)*320 panels; warp w: +w*80.
// ---------------------------------------------------------------------------
__global__ void __launch_bounds__(128, 8) pack_kernel(
        const float* __restrict__ a1, const float* __restrict__ a2) {
    int bid = blockIdx.x;
    int g = bid >> 2, quarter = bid & 3;
    int w = threadIdx.x >> 5, lane = threadIdx.x & 31;

    const char* base = (const char*)(
        (g < BATCH) ? (a1 + (size_t)g * NN * NN)
                    : (a2 + (size_t)(g - BATCH) * NN * NN)) + lane * 16;
    uint4* __restrict__ dst = g_bits4 + (size_t)g * (NN * 4);

    int lp0 = quarter * 320 + w * PPW;
    int iq, irow;
    if      (lp0 < 128) { iq = 0; irow = lp0; }
    else if (lp0 < 384) { iq = 1; irow = lp0 - 128; }
    else if (lp0 < 768) { iq = 2; irow = lp0 - 384; }
    else                { iq = 3; irow = lp0 - 768; }
    int pq = iq, prow = irow;

    float4 v[PDEPTH];

#define K1_ISSUE(slot) {                                                   \
    v[slot] = *(const float4*)(base + irow * 2048 + iq * 512);             \
    if (++irow == ((iq + 1) << 7)) { ++iq; irow = 0; } }

#define K1_PACK(slot) {                                                    \
    float4 x = v[slot];                                                    \
    uint32_t bx = __ballot_sync(0xffffffffu, x.x != 0.0f);                 \
    uint32_t by = __ballot_sync(0xffffffffu, x.y != 0.0f);                 \
    uint32_t bz = __ballot_sync(0xffffffffu, x.z != 0.0f);                 \
    uint32_t bw = __ballot_sync(0xffffffffu, x.w != 0.0f);                 \
    if (lane == 0) dst[prow * 4 + pq] = make_uint4(bx, by, bz, bw);        \
    if (++prow == ((pq + 1) << 7)) { ++pq; prow = 0; } }

#pragma unroll
    for (int p = 0; p < PDEPTH; ++p) K1_ISSUE(p);
#pragma unroll 8
    for (int i = 0; i < PPW - PDEPTH; ++i) { K1_PACK(i & 7); K1_ISSUE(i & 7); }
#pragma unroll
    for (int i = PPW - PDEPTH; i < PPW; ++i) K1_PACK(i & 7);
}

// ---------------------------------------------------------------------------
// K2: per graph -- stage 32KB bitset from L2, mirror lower panels, triangle
// count, histogram; device-wide barrier; RBF-MMD tiles; last-block finalize.
// 256 blocks x 512 thr, 41KB static smem -> 2/SM co-resident (barrier-safe).
// ---------------------------------------------------------------------------
struct MmdStage {
    float xs[16][NBINS + 1];
    float ys[16][NBINS + 1];
    float red[8];
};

__global__ void __launch_bounds__(512, 2) cluster_mmd_kernel(
        float* __restrict__ out) {
    __shared__ __align__(16) union {
        uint4 rows4[NN][RSTR / 4];   // 40960 B (graph phase)
        MmdStage mm;                 // 12960 B (mmd phase)
    } U;
    __shared__ int shist[NBINS];

    int wid  = threadIdx.x >> 5;
    int lane = threadIdx.x & 31;

    if (blockIdx.x == 0 && threadIdx.x < 3) g_acc[threadIdx.x] = 0.0f;
    if (threadIdx.x < NBINS) shist[threadIdx.x] = 0;

    {
        int sb = blockIdx.x;           // graph id 0..255
        int s_ = sb >> 7;
        int b  = sb & (BATCH - 1);

        // ---- stage 32KB bitset (upper panels valid; lower = garbage,
        //      overwritten by mirror below) ----
        const uint4* __restrict__ src = g_bits4 + (size_t)sb * (NN * 4);
#pragma unroll
        for (int k = 0; k < 4; ++k) {
            int e = threadIdx.x + (k << 9);
            U.rows4[e >> 2][e & 3] = src[e];
        }
        __syncthreads();

        // ---- mirror lower panels (R,Q), Q<R, from upper (Q,R) ----
        if (wid < 6) {
            const int RT[6] = {1, 2, 2, 3, 3, 3};
            const int QT[6] = {0, 0, 1, 0, 1, 2};
            int R = RT[wid], Q = QT[wid];
            uint4 u0 = U.rows4[128 * Q + 4 * lane + 0][R];
            uint4 u1 = U.rows4[128 * Q + 4 * lane + 1][R];
            uint4 u2 = U.rows4[128 * Q + 4 * lane + 2][R];
            uint4 u3 = U.rows4[128 * Q + 4 * lane + 3][R];
            u0.x = transpose32(u0.x, lane); u0.y = transpose32(u0.y, lane);
            u0.z = transpose32(u0.z, lane); u0.w = transpose32(u0.w, lane);
            u1.x = transpose32(u1.x, lane); u1.y = transpose32(u1.y, lane);
            u1.z = transpose32(u1.z, lane); u1.w = transpose32(u1.w, lane);
            u2.x = transpose32(u2.x, lane); u2.y = transpose32(u2.y, lane);
            u2.z = transpose32(u2.z, lane); u2.w = transpose32(u2.w, lane);
            u3.x = transpose32(u3.x, lane); u3.y = transpose32(u3.y, lane);
            u3.z = transpose32(u3.z, lane); u3.w = transpose32(u3.w, lane);
            U.rows4[128 * R + 4 * lane + 0][Q] = make_uint4(u0.x, u1.x, u2.x, u3.x);
            U.rows4[128 * R + 4 * lane + 1][Q] = make_uint4(u0.y, u1.y, u2.y, u3.y);
            U.rows4[128 * R + 4 * lane + 2][Q] = make_uint4(u0.z, u1.z, u2.z, u3.z);
            U.rows4[128 * R + 4 * lane + 3][Q] = make_uint4(u0.w, u1.w, u2.w, u3.w);
        }
        __syncthreads();

        // ---- triangles: one thread per node, uniform trips ----
        int i = threadIdx.x;
        uint32_t my[WPR];
        int deg = 0;
        {
            const uint4* r4 = U.rows4[i];
#pragma unroll
            for (int k = 0; k < 4; ++k) {
                uint4 v = r4[k];
                my[4*k]   = v.x; my[4*k+1] = v.y; my[4*k+2] = v.z; my[4*k+3] = v.w;
                deg += __popc(v.x) + __popc(v.y) + __popc(v.z) + __popc(v.w);
            }
        }

        int tri = 0;
        {
            int w = 0;
            uint32_t m = my[0];
            for (int n = 0; n < deg; ++n) {
                while (m == 0) m = my[++w];
                int l = __ffs(m) - 1;
                m &= m - 1;
                int j = (w >> 2) * 128 + 4 * l + (w & 3);   // perm inverse
                const uint4* rj = U.rows4[j];
                int c = 0;
#pragma unroll
                for (int k = 0; k < 4; ++k) {
                    uint4 v = rj[k];
                    c += __popc(my[4*k]   & v.x) + __popc(my[4*k+1] & v.y)
                       + __popc(my[4*k+2] & v.z) + __popc(my[4*k+3] & v.w);
                }
                tri += c;
            }
        }

        // ---- bin (IEEE-exact vs JAX fp32) + histogram ----
        int bin = 0;
        if (deg >= 2) {
            float denom = (float)deg * (float)(deg - 1);
            float c  = __fdiv_rn((float)tri, denom);
            float cb = __fmul_rn(c, (float)NBINS);
            bin = (int)cb;
            bin = bin < 0 ? 0 : (bin > NBINS - 1 ? NBINS - 1 : bin);
        }
        atomicAdd(&shist[bin], 1);
        __syncthreads();

        if (threadIdx.x < NBINS)
            g_histf[s_][b][threadIdx.x] = (float)shist[threadIdx.x];
        __syncthreads();
    }

    // ---- device-wide barrier (all 256 blocks co-resident) ----
    if (threadIdx.x == 0) {
        __threadfence();
        atomicAdd(&g_sync, 1u);
        while (*(volatile unsigned*)&g_sync < (unsigned)NBLK2) { }
    }
    __syncthreads();
    __threadfence();

    // ---- mmd: blocks 0..191 one 16x16 tile each ----
    int t = threadIdx.x;
    if (blockIdx.x < 192) {
        int tile = blockIdx.x;
        int m  = tile >> 6;
        int r  = tile & 63;
        int i0 = (r >> 3) << 4;
        int j0 = (r & 7) << 4;

        const float* __restrict__ hx0 = &g_histf[(m == 1) ? 1 : 0][0][0];
        const float* __restrict__ hy0 = &g_histf[(m == 0) ? 0 : 1][0][0];

        for (int e = t; e < 16 * NBINS; e += 512) {
            int rr = e / NBINS, k = e % NBINS;
            U.mm.xs[rr][k] = hx0[(i0 + rr) * NBINS + k];
            U.mm.ys[rr][k] = hy0[(j0 + rr) * NBINS + k];
        }
        __syncthreads();

        float kv = 0.0f;
        if (t < 256) {
            int ti = t >> 4, tj = t & 15;
            float d2 = 0.0f;
#pragma unroll 4
            for (int k = 0; k < NBINS; ++k) {
                float d = U.mm.xs[ti][k] - U.mm.ys[tj][k];
                d2 = fmaf(d, d, d2);
            }
            kv = expf(-0.5f * d2);
        }
#pragma unroll
        for (int o = 16; o; o >>= 1)
            kv += __shfl_down_sync(0xffffffffu, kv, o);
        if ((t & 31) == 0) U.mm.red[t >> 5] = (t < 256) ? kv : 0.0f;
        __syncthreads();
        if (t < 32) {
            float v = (t < 8) ? U.mm.red[t] : 0.0f;
#pragma unroll
            for (int o = 4; o; o >>= 1)
                v += __shfl_down_sync(0xffffffffu, v, o);
            if (t == 0) atomicAdd(&g_acc[m], v);
        }
        __syncthreads();
    }

    if (t == 0) {
        __threadfence();
        unsigned tk = atomicAdd(&g_done, 1u);
        if (tk == (unsigned)(NBLK2 - 1)) {
            __threadfence();
            const float inv = 1.0f / (128.0f * 128.0f);
            out[0] = (g_acc[0] + g_acc[1] - 2.0f * g_acc[2]) * inv;
            g_done = 0;
            g_sync = 0;
        }
    }
}

// ---------------------------------------------------------------------------
extern "C" void kernel_launch(void* const* d_in, const int* in_sizes, int n_in,
                              void* d_out, int out_size) {
    const float* a1 = (const float*)d_in[0];
    const float* a2 = (const float*)d_in[1];

    pack_kernel<<<1024, 128>>>(a1, a2);
    cluster_mmd_kernel<<<NBLK2, 512>>>((float*)d_out);
}